// round 15
// baseline (speedup 1.0000x reference)
#include <cuda_runtime.h>
#include <cuda_bf16.h>
#include <cuda_fp16.h>

#define BB 4
#define CC 256
#define CQ 32
#define NN 4096      // 64*64 spatial
#define NTILES 256   // NN / 16 (m-tiles of 16 energy-cols)
#define LOG2E 1.4426950408889634f

// Scratch (device globals: allocation-free per harness rules)
__device__ float g_q[BB*NN*CQ];                 // (b, n, o) fp32 (PRE-SCALED by log2e), 2 MB
// k pre-blocked into exact mma.sync m16n8k16 fp16 A-fragment layout:
// index ((b*NTILES + T)*2 + s)*32 + lane -> uint4 = regs {a0,a1,a2,a3}
__device__ uint4 g_ka[BB*NTILES*2*32];          // 1 MB total (2 B/elem)

#define KA_BSTRIDE ((size_t)NTILES*2*32)        // batch stride in uint4

// ---------------------------------------------------------------------------
// helpers
// ---------------------------------------------------------------------------
__device__ __forceinline__ void mma_f16(float* d, const uint4& a,
                                        unsigned b0, unsigned b1)
{
    asm volatile(
        "mma.sync.aligned.m16n8k16.row.col.f32.f16.f16.f32 "
        "{%0,%1,%2,%3}, {%4,%5,%6,%7}, {%8,%9}, {%0,%1,%2,%3};"
        : "+f"(d[0]), "+f"(d[1]), "+f"(d[2]), "+f"(d[3])
        : "r"(a.x), "r"(a.y), "r"(a.z), "r"(a.w), "r"(b0), "r"(b1));
}

__device__ __forceinline__ unsigned pack_f16(float a, float b)
{
    __half2 h = __floats2half2_rn(a, b);        // .x = a = low 16 bits
    unsigned u; memcpy(&u, &h, 4); return u;
}

__device__ __forceinline__ float ex2(float x)
{
    float r; asm("ex2.approx.ftz.f32 %0, %1;" : "=f"(r) : "f"(x)); return r;
}

__device__ __forceinline__ unsigned smem_u32(const void* p)
{
    unsigned a;
    asm("{ .reg .u64 t; cvta.to.shared.u64 t, %1; cvt.u32.u64 %0, t; }"
        : "=r"(a) : "l"(p));
    return a;
}

__device__ __forceinline__ unsigned ctarank()
{
    unsigned r; asm("mov.u32 %0, %%cluster_ctarank;" : "=r"(r)); return r;
}

__device__ __forceinline__ void st_peer_f32(unsigned local_addr, unsigned peer,
                                            float v)
{
    asm volatile(
        "{ .reg .b32 r; mapa.shared::cluster.u32 r, %0, %1; "
        "st.shared::cluster.f32 [r], %2; }"
        :: "r"(local_addr), "r"(peer), "f"(v) : "memory");
}

// ---------------------------------------------------------------------------
// Kernel A (proven R14): TENSOR-CORE q/k projection.
// D-frag layout == attn A-frag layout -> k fragments emitted directly from
// accumulators; q written fp32 (+bias, *log2e).
// ---------------------------------------------------------------------------
#define XROW 258                                  // padded row (halves)
#define PSMEM (64*XROW*2*2 + 64*4)                // xs + ws + bias = 66,304 B

__global__ __launch_bounds__(128) void proj_qk_tc(
    const float* __restrict__ x,
    const float* __restrict__ wq, const float* __restrict__ bq,
    const float* __restrict__ wk, const float* __restrict__ bk)
{
    extern __shared__ __half psm[];
    __half* xs   = psm;                 // [64 n][XROW c]
    __half* ws   = psm + 64*XROW;       // [64 ch][XROW c] (0..31 wq, 32..63 wk)
    float*  bias = (float*)(ws + 64*XROW);   // [64]

    const int b  = blockIdx.y;
    const int n0 = blockIdx.x * 64;
    const int t  = threadIdx.x;
    const float* xb = x + (size_t)b*CC*NN;

    if (t < 64) bias[t] = (t < 32) ? bq[t] : bk[t - 32];

    for (int i = t; i < 64*64; i += 128) {
        int row = i >> 6, c4 = (i & 63) * 4;
        const float* wr = (row < 32) ? (wq + (size_t)row*CC)
                                     : (wk + (size_t)(row-32)*CC);
        float4 v = *(const float4*)(wr + c4);
        __half* dst = ws + row*XROW + c4;
        *(__half2*)(dst)     = __floats2half2_rn(v.x, v.y);
        *(__half2*)(dst + 2) = __floats2half2_rn(v.z, v.w);
    }

    for (int i = t; i < 128*16; i += 128) {
        int cp = i >> 4, j4 = i & 15;
        const float* r0 = xb + (size_t)(2*cp    )*NN + n0 + j4*4;
        const float* r1 = xb + (size_t)(2*cp + 1)*NN + n0 + j4*4;
        float4 a = *(const float4*)r0;
        float4 c = *(const float4*)r1;
        *(__half2*)&xs[(j4*4+0)*XROW + 2*cp] = __floats2half2_rn(a.x, c.x);
        *(__half2*)&xs[(j4*4+1)*XROW + 2*cp] = __floats2half2_rn(a.y, c.y);
        *(__half2*)&xs[(j4*4+2)*XROW + 2*cp] = __floats2half2_rn(a.z, c.z);
        *(__half2*)&xs[(j4*4+3)*XROW + 2*cp] = __floats2half2_rn(a.w, c.w);
    }
    __syncthreads();

    const int warp = t >> 5, lane = t & 31;
    const int g4 = lane >> 2, tig = lane & 3;
    const int m0 = warp * 16;

    float acc[8][4];
    #pragma unroll
    for (int nt = 0; nt < 8; nt++)
        #pragma unroll
        for (int e = 0; e < 4; e++) acc[nt][e] = 0.f;

    #pragma unroll 4
    for (int ks = 0; ks < 16; ks++) {
        const int c0 = ks*16 + tig*2;
        uint4 A;
        A.x = *(unsigned*)&xs[(m0 + g4    )*XROW + c0];
        A.y = *(unsigned*)&xs[(m0 + g4 + 8)*XROW + c0];
        A.z = *(unsigned*)&xs[(m0 + g4    )*XROW + c0 + 8];
        A.w = *(unsigned*)&xs[(m0 + g4 + 8)*XROW + c0 + 8];
        #pragma unroll
        for (int nt = 0; nt < 8; nt++) {
            unsigned b0 = *(unsigned*)&ws[(nt*8 + g4)*XROW + c0];
            unsigned b1 = *(unsigned*)&ws[(nt*8 + g4)*XROW + c0 + 8];
            mma_f16(acc[nt], A, b0, b1);
        }
    }

    #pragma unroll
    for (int nt = 0; nt < 4; nt++) {
        const int ch = nt*8 + tig*2;
        const float b0v = bias[ch], b1v = bias[ch+1];
        const int nrow = n0 + m0 + g4;
        float2 q0, q1;
        q0.x = (acc[nt][0] + b0v) * LOG2E;
        q0.y = (acc[nt][1] + b1v) * LOG2E;
        q1.x = (acc[nt][2] + b0v) * LOG2E;
        q1.y = (acc[nt][3] + b1v) * LOG2E;
        *(float2*)&g_q[((size_t)b*NN + nrow    )*CQ + ch] = q0;
        *(float2*)&g_q[((size_t)b*NN + nrow + 8)*CQ + ch] = q1;
    }

    const int T = blockIdx.x*4 + warp;
    #pragma unroll
    for (int s = 0; s < 2; s++) {
        const int ntA = 4 + s*2, ntB = ntA + 1;
        const int chA = s*16 + tig*2;
        const int chB = chA + 8;
        const float bA0 = bias[32 + chA], bA1 = bias[32 + chA + 1];
        const float bB0 = bias[32 + chB], bB1 = bias[32 + chB + 1];
        uint4 frag;
        frag.x = pack_f16(acc[ntA][0] + bA0, acc[ntA][1] + bA1);
        frag.y = pack_f16(acc[ntA][2] + bA0, acc[ntA][3] + bA1);
        frag.z = pack_f16(acc[ntB][0] + bB0, acc[ntB][1] + bB1);
        frag.w = pack_f16(acc[ntB][2] + bB0, acc[ntB][3] + bB1);
        g_ka[((size_t)(b*NTILES + T)*2 + s)*32 + lane] = frag;
    }
}

// ---------------------------------------------------------------------------
// Kernel B v9: cluster(2) column-split attention, R=32 rows/CTA.
// k L2 read traffic halves vs v8 (128 MB total): traffic = const/R, and
// R13 proved 2 CTAs/SM buys nothing, so occupancy is spent on R.
// Each CTA: 32 rows x 2048 cols; stash 32x2056 fp16 = 131.5 KB (1 CTA/SM).
// grid.x = 256 (rowblock*2 + colhalf), cluster (2,1,1).
// ---------------------------------------------------------------------------
#define RS2 2056                               // stash row stride in halves
#define ATTN_SMEM (1024*4 + 32*4 + 32*4 + 32*RS2*2)   // 135,936 B

__global__ __launch_bounds__(512, 1) __cluster_dims__(2, 1, 1)
void attn_kernel(
    float* __restrict__ att,
    const float* __restrict__ x, const float* __restrict__ gamma,
    float* __restrict__ out)
{
    extern __shared__ char smraw[];
    float*  qs        = (float*)smraw;          // [32][32]
    float*  ssum      = qs + 1024;              // [32] local partials
    float*  ssum_peer = ssum + 32;              // [32] written by peer CTA
    __half* stash     = (__half*)(ssum_peer + 32);   // [32][RS2]

    const int b        = blockIdx.y;
    const int rowblock = blockIdx.x >> 1;
    const int colhalf  = blockIdx.x & 1;
    const int i0 = rowblock * 32;
    const int t  = threadIdx.x;

    // fused out = x copy (independent work, drains behind the mainloop)
    if (gamma[0] == 0.0f) {
        const int gid = b * gridDim.x + blockIdx.x;    // 0..1023
        const size_t i4 = (size_t)gid*1024 + t;        // 1024*1024 = OUT_N/4
        ((float4*)out)[i4]       = ((const float4*)x)[i4];
        ((float4*)out)[i4 + 512] = ((const float4*)x)[i4 + 512];
    }

    qs[t]       = g_q[((size_t)b*NN + i0 + (t>>5)      )*CQ + (t&31)];
    qs[t + 512] = g_q[((size_t)b*NN + i0 + (t>>5) + 16 )*CQ + (t&31)];
    if (t < 32) { ssum[t] = 0.f; }
    __syncthreads();

    const int warp = t >> 5, lane = t & 31;
    const int g4 = lane >> 2, tig = lane & 3;

    // fp16 B-fragments from q for 4 row-groups x 2 ksteps
    unsigned bq0[4][2], bq1[4][2];
    #pragma unroll
    for (int grp = 0; grp < 4; grp++) {
        #pragma unroll
        for (int s = 0; s < 2; s++) {
            const float* qr = &qs[(grp*8 + g4)*CQ + s*16 + tig*2];
            bq0[grp][s] = pack_f16(qr[0], qr[1]);
            bq1[grp][s] = pack_f16(qr[8], qr[9]);
        }
    }

    const uint4* ka = g_ka + (size_t)b * KA_BSTRIDE;
    const int tbase = colhalf*128 + warp*8;      // 8 tiles of 16 cols per warp

    float rs0[4] = {0.f, 0.f, 0.f, 0.f};   // i = grp*8 + tig*2
    float rs1[4] = {0.f, 0.f, 0.f, 0.f};   // i = grp*8 + tig*2 + 1

    // depth-2 prefetch ring over this warp's 8 tiles
    uint4 P0[2], P1[2];
    #pragma unroll
    for (int dd = 0; dd < 2; dd++) {
        int T = tbase + dd;
        P0[dd] = ka[(size_t)(T*2  )*32 + lane];
        P1[dd] = ka[(size_t)(T*2+1)*32 + lane];
    }

    #pragma unroll
    for (int tt = 0; tt < 8; tt++) {
        const int slot = tt & 1;
        uint4 cA0 = P0[slot], cA1 = P1[slot];
        if (tt + 2 < 8) {
            int Tn = tbase + tt + 2;
            P0[slot] = ka[(size_t)(Tn*2  )*32 + lane];
            P1[slot] = ka[(size_t)(Tn*2+1)*32 + lane];
        }

        float d[4][4];
        #pragma unroll
        for (int grp = 0; grp < 4; grp++)
            #pragma unroll
            for (int e = 0; e < 4; e++) d[grp][e] = 0.f;

        #pragma unroll
        for (int grp = 0; grp < 4; grp++) {
            mma_f16(d[grp], cA0, bq0[grp][0], bq1[grp][0]);
            mma_f16(d[grp], cA1, bq0[grp][1], bq1[grp][1]);
        }

        // ex2 (q pre-scaled by log2e), rowsums, conflict-free fp16 stash
        const int pos = (warp*8 + tt)*16 + g4*2;     // local-column coords
        #pragma unroll
        for (int grp = 0; grp < 4; grp++) {
            const int i0r = grp*8 + tig*2;
            float p0 = ex2(d[grp][0]);
            float p1 = ex2(d[grp][1]);
            float p2 = ex2(d[grp][2]);
            float p3 = ex2(d[grp][3]);
            rs0[grp] += p0 + p2;
            rs1[grp] += p1 + p3;
            *(__half2*)&stash[(i0r  )*RS2 + pos] = __floats2half2_rn(p0, p2);
            *(__half2*)&stash[(i0r+1)*RS2 + pos] = __floats2half2_rn(p1, p3);
        }
    }

    // intra-CTA reduction: lanes sharing tig (g4 varies -> masks 4,8,16)
    #pragma unroll
    for (int grp = 0; grp < 4; grp++) {
        #pragma unroll
        for (int m = 4; m <= 16; m <<= 1) {
            rs0[grp] += __shfl_xor_sync(0xffffffffu, rs0[grp], m);
            rs1[grp] += __shfl_xor_sync(0xffffffffu, rs1[grp], m);
        }
    }
    if (g4 == 0) {
        #pragma unroll
        for (int grp = 0; grp < 4; grp++) {
            atomicAdd(&ssum[grp*8 + tig*2    ], rs0[grp]);
            atomicAdd(&ssum[grp*8 + tig*2 + 1], rs1[grp]);
        }
    }
    __syncthreads();

    // cross-CTA rowsum exchange
    {
        const unsigned peer = ctarank() ^ 1u;
        if (t < 32)
            st_peer_f32(smem_u32(&ssum_peer[t]), peer, ssum[t]);
    }
    asm volatile("barrier.cluster.arrive.aligned;" ::: "memory");
    asm volatile("barrier.cluster.wait.aligned;"  ::: "memory");

    // normalize + store: warp handles 2 rows x 2048 cols
    #pragma unroll
    for (int rr = 0; rr < 2; rr++) {
        const int r  = warp*2 + rr;
        const float inv = 1.0f / (ssum[r] + ssum_peer[r]);
        float* arow = att + ((size_t)b*NN + i0 + r)*NN + colhalf*2048;
        const __half* srow = stash + r*RS2;
        #pragma unroll 4
        for (int u = 0; u < 8; u++) {
            int p0 = lane*8 + u*256;
            uint4 raw = *(const uint4*)(srow + p0);
            const __half2* hp = (const __half2*)&raw;
            float2 f0 = __half22float2(hp[0]);
            float2 f1 = __half22float2(hp[1]);
            float2 f2 = __half22float2(hp[2]);
            float2 f3 = __half22float2(hp[3]);
            int jA = (p0 >> 4)*16 + ((p0 & 15) >> 1);
            float4 wA, wB;
            wA.x = f0.x*inv; wA.y = f1.x*inv; wA.z = f2.x*inv; wA.w = f3.x*inv;
            wB.x = f0.y*inv; wB.y = f1.y*inv; wB.z = f2.y*inv; wB.w = f3.y*inv;
            *(float4*)(arow + jA)     = wA;
            *(float4*)(arow + jA + 8) = wB;
        }
    }
}

// ---------------------------------------------------------------------------
// Merged generic fallback (gamma != 0 only): computes v inline per (b,c) and
// out = gamma*(att@v^T) + x. Replaces proj_v + out_fallback (one launch).
// ---------------------------------------------------------------------------
__global__ __launch_bounds__(256) void out_fallback_kernel(
    const float* __restrict__ x, const float* __restrict__ gamma,
    const float* __restrict__ wv, const float* __restrict__ bv,
    const float* __restrict__ att, float* __restrict__ out)
{
    const float g = gamma[0];
    if (g == 0.0f || att == nullptr) return;
    __shared__ float vrow[NN];                 // 16 KB
    const int pc = blockIdx.x;                 // 0..BB*CC-1
    const int b = pc / CC, c = pc % CC;
    const float* xb = x + (size_t)b*CC*NN;
    const float* wr = wv + (size_t)c*CC;
    const float bvc = bv[c];
    for (int j = threadIdx.x; j < NN; j += 256) {
        float s = bvc;
        for (int ch = 0; ch < CC; ch++) s += wr[ch] * xb[(size_t)ch*NN + j];
        vrow[j] = s;
    }
    __syncthreads();
    const float* ab = att + (size_t)b*NN*NN;
    for (int i = threadIdx.x; i < NN; i += 256) {
        float s = 0.f;
        const float* ar = ab + (size_t)i*NN;
        for (int j = 0; j < NN; j++) s += vrow[j] * ar[j];
        const size_t idx = ((size_t)b*CC + c)*NN + i;
        out[idx] = g*s + x[idx];
    }
}

// ---------------------------------------------------------------------------
__global__ __launch_bounds__(256) void copy_kernel(
    const float* __restrict__ x, float* __restrict__ out)
{
    const size_t i4 = (size_t)blockIdx.x*256 + threadIdx.x;
    ((float4*)out)[i4] = ((const float4*)x)[i4];
}

// ---------------------------------------------------------------------------
extern "C" void kernel_launch(void* const* d_in, const int* in_sizes, int n_in,
                              void* d_out, int out_size)
{
    const float* x     = (const float*)d_in[0];
    const float* wq    = (const float*)d_in[1];
    const float* bq    = (const float*)d_in[2];
    const float* wk    = (const float*)d_in[3];
    const float* bk    = (const float*)d_in[4];
    const float* wv    = (const float*)d_in[5];
    const float* bv    = (const float*)d_in[6];
    const float* gamma = (const float*)d_in[7];
    float* out = (float*)d_out;

    const int OUT_N = BB*CC*NN;        // 4,194,304
    const int ATT_N = BB*NN*NN;        // 67,108,864

    float* out_ptr = nullptr;
    float* att_ptr = nullptr;
    if (out_size >= OUT_N + ATT_N)      { out_ptr = out; att_ptr = out + OUT_N; }
    else if (out_size == ATT_N)         { att_ptr = out; }
    else                                { out_ptr = out; }

    cudaFuncSetAttribute(proj_qk_tc,
                         cudaFuncAttributeMaxDynamicSharedMemorySize, PSMEM);
    cudaFuncSetAttribute(attn_kernel,
                         cudaFuncAttributeMaxDynamicSharedMemorySize, ATTN_SMEM);

    proj_qk_tc<<<dim3(NN/64, BB), 128, PSMEM>>>(x, wq, bq, wk, bk);
    if (att_ptr && out_ptr) {
        attn_kernel<<<dim3(256, BB), 512, ATTN_SMEM>>>(att_ptr, x, gamma, out_ptr);
        out_fallback_kernel<<<BB*CC, 256>>>(x, gamma, wv, bv, att_ptr, out_ptr);
    } else if (att_ptr) {
        attn_kernel<<<dim3(256, BB), 512, ATTN_SMEM>>>(att_ptr, x, gamma, att_ptr);
    } else if (out_ptr) {
        copy_kernel<<<(OUT_N/4)/256, 256>>>(x, out_ptr);
        out_fallback_kernel<<<BB*CC, 256>>>(x, gamma, wv, bv, nullptr, out_ptr);
    }
}

// round 17
// speedup vs baseline: 1.0647x; 1.0647x over previous
#include <cuda_runtime.h>
#include <cuda_bf16.h>
#include <cuda_fp16.h>

#define BB 4
#define CC 256
#define CQ 32
#define NN 4096      // 64*64 spatial
#define NTILES 256   // NN / 16 (m-tiles of 16 energy-cols)
#define LOG2E 1.4426950408889634f

// Scratch (device globals: allocation-free per harness rules)
__device__ float g_q[BB*NN*CQ];                 // (b, n, o) fp32 (PRE-SCALED by log2e), 2 MB
// k pre-blocked into exact mma.sync m16n8k16 fp16 A-fragment layout:
// index ((b*NTILES + T)*2 + s)*32 + lane -> uint4 = regs {a0,a1,a2,a3}
__device__ uint4 g_ka[BB*NTILES*2*32];          // 1 MB total (2 B/elem)

#define KA_BSTRIDE ((size_t)NTILES*2*32)        // batch stride in uint4

// ---------------------------------------------------------------------------
// helpers
// ---------------------------------------------------------------------------
__device__ __forceinline__ void mma_f16(float* d, const uint4& a,
                                        unsigned b0, unsigned b1)
{
    asm volatile(
        "mma.sync.aligned.m16n8k16.row.col.f32.f16.f16.f32 "
        "{%0,%1,%2,%3}, {%4,%5,%6,%7}, {%8,%9}, {%0,%1,%2,%3};"
        : "+f"(d[0]), "+f"(d[1]), "+f"(d[2]), "+f"(d[3])
        : "r"(a.x), "r"(a.y), "r"(a.z), "r"(a.w), "r"(b0), "r"(b1));
}

__device__ __forceinline__ unsigned pack_f16(float a, float b)
{
    __half2 h = __floats2half2_rn(a, b);        // .x = a = low 16 bits
    unsigned u; memcpy(&u, &h, 4); return u;
}

__device__ __forceinline__ float ex2(float x)
{
    float r; asm("ex2.approx.ftz.f32 %0, %1;" : "=f"(r) : "f"(x)); return r;
}

__device__ __forceinline__ unsigned smem_u32(const void* p)
{
    unsigned a;
    asm("{ .reg .u64 t; cvta.to.shared.u64 t, %1; cvt.u32.u64 %0, t; }"
        : "=r"(a) : "l"(p));
    return a;
}

__device__ __forceinline__ unsigned ctarank()
{
    unsigned r; asm("mov.u32 %0, %%cluster_ctarank;" : "=r"(r)); return r;
}

__device__ __forceinline__ void st_peer_f32(unsigned local_addr, unsigned peer,
                                            float v)
{
    asm volatile(
        "{ .reg .b32 r; mapa.shared::cluster.u32 r, %0, %1; "
        "st.shared::cluster.f32 [r], %2; }"
        :: "r"(local_addr), "r"(peer), "f"(v) : "memory");
}

// ---------------------------------------------------------------------------
// Kernel A v5: TENSOR-CORE q/k projection, 256 threads (8 warps), warp-split
// over ntiles: warps 0-3 -> ntiles 0-3 (q), warps 4-7 -> ntiles 4-7 (k).
// Same 64-row tile/smem as v4 (occ-limited before: 4 warps, issue 6.9%).
// Per-warp MMA count halves (64), epilogue halves, loads 2x wider.
// ---------------------------------------------------------------------------
#define XROW 258                                  // padded row (halves)
#define PSMEM (64*XROW*2*2 + 64*4)                // xs + ws + bias = 66,304 B

__global__ __launch_bounds__(256) void proj_qk_tc(
    const float* __restrict__ x,
    const float* __restrict__ wq, const float* __restrict__ bq,
    const float* __restrict__ wk, const float* __restrict__ bk)
{
    extern __shared__ __half psm[];
    __half* xs   = psm;                 // [64 n][XROW c]
    __half* ws   = psm + 64*XROW;       // [64 ch][XROW c] (0..31 wq, 32..63 wk)
    float*  bias = (float*)(ws + 64*XROW);   // [64]

    const int b  = blockIdx.y;
    const int n0 = blockIdx.x * 64;
    const int t  = threadIdx.x;
    const float* xb = x + (size_t)b*CC*NN;

    if (t < 64) bias[t] = (t < 32) ? bq[t] : bk[t - 32];

    // w -> smem fp16
    for (int i = t; i < 64*64; i += 256) {
        int row = i >> 6, c4 = (i & 63) * 4;
        const float* wr = (row < 32) ? (wq + (size_t)row*CC)
                                     : (wk + (size_t)(row-32)*CC);
        float4 v = *(const float4*)(wr + c4);
        __half* dst = ws + row*XROW + c4;
        *(__half2*)(dst)     = __floats2half2_rn(v.x, v.y);
        *(__half2*)(dst + 2) = __floats2half2_rn(v.z, v.w);
    }

    // x tile -> smem fp16 transposed [n][c]
    for (int i = t; i < 128*16; i += 256) {
        int cp = i >> 4, j4 = i & 15;
        const float* r0 = xb + (size_t)(2*cp    )*NN + n0 + j4*4;
        const float* r1 = xb + (size_t)(2*cp + 1)*NN + n0 + j4*4;
        float4 a = *(const float4*)r0;
        float4 c = *(const float4*)r1;
        *(__half2*)&xs[(j4*4+0)*XROW + 2*cp] = __floats2half2_rn(a.x, c.x);
        *(__half2*)&xs[(j4*4+1)*XROW + 2*cp] = __floats2half2_rn(a.y, c.y);
        *(__half2*)&xs[(j4*4+2)*XROW + 2*cp] = __floats2half2_rn(a.z, c.z);
        *(__half2*)&xs[(j4*4+3)*XROW + 2*cp] = __floats2half2_rn(a.w, c.w);
    }
    __syncthreads();

    const int warp = t >> 5, lane = t & 31;
    const int g4 = lane >> 2, tig = lane & 3;
    const int rw   = warp & 3;                 // row-group (0..3)
    const int wgrp = warp >> 2;                // 0 = q-ntiles, 1 = k-ntiles
    const int m0   = rw * 16;                  // spatial rows of this warp

    float acc[4][4];                           // 4 local ntiles
    #pragma unroll
    for (int nt = 0; nt < 4; nt++)
        #pragma unroll
        for (int e = 0; e < 4; e++) acc[nt][e] = 0.f;

    #pragma unroll 4
    for (int ks = 0; ks < 16; ks++) {
        const int c0 = ks*16 + tig*2;
        uint4 A;                                // attn-validated A layout
        A.x = *(unsigned*)&xs[(m0 + g4    )*XROW + c0];
        A.y = *(unsigned*)&xs[(m0 + g4 + 8)*XROW + c0];
        A.z = *(unsigned*)&xs[(m0 + g4    )*XROW + c0 + 8];
        A.w = *(unsigned*)&xs[(m0 + g4 + 8)*XROW + c0 + 8];
        #pragma unroll
        for (int nt = 0; nt < 4; nt++) {
            const int gnt = wgrp*4 + nt;
            unsigned b0 = *(unsigned*)&ws[(gnt*8 + g4)*XROW + c0];
            unsigned b1 = *(unsigned*)&ws[(gnt*8 + g4)*XROW + c0 + 8];
            mma_f16(acc[nt], A, b0, b1);
        }
    }

    if (wgrp == 0) {
        // q epilogue (global ntiles 0-3): + bias, * log2e, float2 stores
        #pragma unroll
        for (int nt = 0; nt < 4; nt++) {
            const int ch = nt*8 + tig*2;
            const float b0v = bias[ch], b1v = bias[ch+1];
            const int nrow = n0 + m0 + g4;
            float2 q0, q1;
            q0.x = (acc[nt][0] + b0v) * LOG2E;
            q0.y = (acc[nt][1] + b1v) * LOG2E;
            q1.x = (acc[nt][2] + b0v) * LOG2E;
            q1.y = (acc[nt][3] + b1v) * LOG2E;
            *(float2*)&g_q[((size_t)b*NN + nrow    )*CQ + ch] = q0;
            *(float2*)&g_q[((size_t)b*NN + nrow + 8)*CQ + ch] = q1;
        }
    } else {
        // k epilogue (global ntiles 4-7 = local 0-3): attn A-frags from regs
        const int T = blockIdx.x*4 + rw;
        #pragma unroll
        for (int s = 0; s < 2; s++) {
            const int ntA = s*2, ntB = ntA + 1;       // local indices
            const int chA = s*16 + tig*2;
            const int chB = chA + 8;
            const float bA0 = bias[32 + chA], bA1 = bias[32 + chA + 1];
            const float bB0 = bias[32 + chB], bB1 = bias[32 + chB + 1];
            uint4 frag;
            frag.x = pack_f16(acc[ntA][0] + bA0, acc[ntA][1] + bA1);
            frag.y = pack_f16(acc[ntA][2] + bA0, acc[ntA][3] + bA1);
            frag.z = pack_f16(acc[ntB][0] + bB0, acc[ntB][1] + bB1);
            frag.w = pack_f16(acc[ntB][2] + bB0, acc[ntB][3] + bB1);
            g_ka[((size_t)(b*NTILES + T)*2 + s)*32 + lane] = frag;
        }
    }
}

// ---------------------------------------------------------------------------
// Kernel B v8 (reverted to the R13/R14-proven config): cluster(2) column-split
// attention, R=16 rows/CTA, 2 CTAs/SM.
// ---------------------------------------------------------------------------
#define RS2 2056                               // stash row stride in halves
#define ATTN_SMEM (512*4 + 16*4 + 16*4 + 16*RS2*2)   // 67,968 B

__global__ __launch_bounds__(512, 2) __cluster_dims__(2, 1, 1)
void attn_kernel(
    float* __restrict__ att,
    const float* __restrict__ x, const float* __restrict__ gamma,
    float* __restrict__ out)
{
    extern __shared__ char smraw[];
    float*  qs        = (float*)smraw;          // [16][32]
    float*  ssum      = qs + 512;               // [16] local partials
    float*  ssum_peer = ssum + 16;              // [16] written by peer CTA
    __half* stash     = (__half*)(ssum_peer + 16);   // [16][RS2]

    const int b        = blockIdx.y;
    const int rowblock = blockIdx.x >> 1;
    const int colhalf  = blockIdx.x & 1;
    const int i0 = rowblock * 16;
    const int t  = threadIdx.x;

    // fused out = x copy (independent work, drains behind the mainloop)
    if (gamma[0] == 0.0f) {
        const int gid = b * gridDim.x + blockIdx.x;    // 0..2047
        const size_t i4 = (size_t)gid*512 + t;         // 2048*512 = OUT_N/4
        ((float4*)out)[i4] = ((const float4*)x)[i4];
    }

    qs[t] = g_q[((size_t)b*NN + i0 + (t>>5))*CQ + (t&31)];
    if (t < 16) { ssum[t] = 0.f; }
    __syncthreads();

    const int warp = t >> 5, lane = t & 31;
    const int g4 = lane >> 2, tig = lane & 3;

    unsigned bq0[2][2], bq1[2][2];
    #pragma unroll
    for (int grp = 0; grp < 2; grp++) {
        #pragma unroll
        for (int s = 0; s < 2; s++) {
            const float* qr = &qs[(grp*8 + g4)*CQ + s*16 + tig*2];
            bq0[grp][s] = pack_f16(qr[0], qr[1]);
            bq1[grp][s] = pack_f16(qr[8], qr[9]);
        }
    }

    const uint4* ka = g_ka + (size_t)b * KA_BSTRIDE;
    const int tbase = colhalf*128 + warp*8;

    float rs0[2] = {0.f, 0.f};
    float rs1[2] = {0.f, 0.f};

    uint4 P0[2], P1[2];
    #pragma unroll
    for (int dd = 0; dd < 2; dd++) {
        int T = tbase + dd;
        P0[dd] = ka[(size_t)(T*2  )*32 + lane];
        P1[dd] = ka[(size_t)(T*2+1)*32 + lane];
    }

    #pragma unroll
    for (int tt = 0; tt < 8; tt++) {
        const int slot = tt & 1;
        uint4 cA0 = P0[slot], cA1 = P1[slot];
        if (tt + 2 < 8) {
            int Tn = tbase + tt + 2;
            P0[slot] = ka[(size_t)(Tn*2  )*32 + lane];
            P1[slot] = ka[(size_t)(Tn*2+1)*32 + lane];
        }

        float d[2][4];
        #pragma unroll
        for (int grp = 0; grp < 2; grp++)
            #pragma unroll
            for (int e = 0; e < 4; e++) d[grp][e] = 0.f;

        #pragma unroll
        for (int grp = 0; grp < 2; grp++) {
            mma_f16(d[grp], cA0, bq0[grp][0], bq1[grp][0]);
            mma_f16(d[grp], cA1, bq0[grp][1], bq1[grp][1]);
        }

        const int pos = (warp*8 + tt)*16 + g4*2;
        #pragma unroll
        for (int grp = 0; grp < 2; grp++) {
            const int i0r = grp*8 + tig*2;
            float p0 = ex2(d[grp][0]);
            float p1 = ex2(d[grp][1]);
            float p2 = ex2(d[grp][2]);
            float p3 = ex2(d[grp][3]);
            rs0[grp] += p0 + p2;
            rs1[grp] += p1 + p3;
            *(__half2*)&stash[(i0r  )*RS2 + pos] = __floats2half2_rn(p0, p2);
            *(__half2*)&stash[(i0r+1)*RS2 + pos] = __floats2half2_rn(p1, p3);
        }
    }

    #pragma unroll
    for (int grp = 0; grp < 2; grp++) {
        #pragma unroll
        for (int m = 4; m <= 16; m <<= 1) {
            rs0[grp] += __shfl_xor_sync(0xffffffffu, rs0[grp], m);
            rs1[grp] += __shfl_xor_sync(0xffffffffu, rs1[grp], m);
        }
    }
    if (g4 == 0) {
        #pragma unroll
        for (int grp = 0; grp < 2; grp++) {
            atomicAdd(&ssum[grp*8 + tig*2    ], rs0[grp]);
            atomicAdd(&ssum[grp*8 + tig*2 + 1], rs1[grp]);
        }
    }
    __syncthreads();

    {
        const unsigned peer = ctarank() ^ 1u;
        if (t < 16)
            st_peer_f32(smem_u32(&ssum_peer[t]), peer, ssum[t]);
    }
    asm volatile("barrier.cluster.arrive.aligned;" ::: "memory");
    asm volatile("barrier.cluster.wait.aligned;"  ::: "memory");

    {
        const int r  = warp;
        const float inv = 1.0f / (ssum[r] + ssum_peer[r]);
        float* arow = att + ((size_t)b*NN + i0 + r)*NN + colhalf*2048;
        const __half* srow = stash + r*RS2;
        #pragma unroll 4
        for (int u = 0; u < 8; u++) {
            int p0 = lane*8 + u*256;
            uint4 raw = *(const uint4*)(srow + p0);
            const __half2* hp = (const __half2*)&raw;
            float2 f0 = __half22float2(hp[0]);
            float2 f1 = __half22float2(hp[1]);
            float2 f2 = __half22float2(hp[2]);
            float2 f3 = __half22float2(hp[3]);
            int jA = (p0 >> 4)*16 + ((p0 & 15) >> 1);
            float4 wA, wB;
            wA.x = f0.x*inv; wA.y = f1.x*inv; wA.z = f2.x*inv; wA.w = f3.x*inv;
            wB.x = f0.y*inv; wB.y = f1.y*inv; wB.z = f2.y*inv; wB.w = f3.y*inv;
            *(float4*)(arow + jA)     = wA;
            *(float4*)(arow + jA + 8) = wB;
        }
    }
}

// ---------------------------------------------------------------------------
// Merged generic fallback (gamma != 0 only): computes v inline per (b,c) and
// out = gamma*(att@v^T) + x.
// ---------------------------------------------------------------------------
__global__ __launch_bounds__(256) void out_fallback_kernel(
    const float* __restrict__ x, const float* __restrict__ gamma,
    const float* __restrict__ wv, const float* __restrict__ bv,
    const float* __restrict__ att, float* __restrict__ out)
{
    const float g = gamma[0];
    if (g == 0.0f || att == nullptr) return;
    __shared__ float vrow[NN];                 // 16 KB
    const int pc = blockIdx.x;                 // 0..BB*CC-1
    const int b = pc / CC, c = pc % CC;
    const float* xb = x + (size_t)b*CC*NN;
    const float* wr = wv + (size_t)c*CC;
    const float bvc = bv[c];
    for (int j = threadIdx.x; j < NN; j += 256) {
        float s = bvc;
        for (int ch = 0; ch < CC; ch++) s += wr[ch] * xb[(size_t)ch*NN + j];
        vrow[j] = s;
    }
    __syncthreads();
    const float* ab = att + (size_t)b*NN*NN;
    for (int i = threadIdx.x; i < NN; i += 256) {
        float s = 0.f;
        const float* ar = ab + (size_t)i*NN;
        for (int j = 0; j < NN; j++) s += vrow[j] * ar[j];
        const size_t idx = ((size_t)b*CC + c)*NN + i;
        out[idx] = g*s + x[idx];
    }
}

// ---------------------------------------------------------------------------
__global__ __launch_bounds__(256) void copy_kernel(
    const float* __restrict__ x, float* __restrict__ out)
{
    const size_t i4 = (size_t)blockIdx.x*256 + threadIdx.x;
    ((float4*)out)[i4] = ((const float4*)x)[i4];
}

// ---------------------------------------------------------------------------
extern "C" void kernel_launch(void* const* d_in, const int* in_sizes, int n_in,
                              void* d_out, int out_size)
{
    const float* x     = (const float*)d_in[0];
    const float* wq    = (const float*)d_in[1];
    const float* bq    = (const float*)d_in[2];
    const float* wk    = (const float*)d_in[3];
    const float* bk    = (const float*)d_in[4];
    const float* wv    = (const float*)d_in[5];
    const float* bv    = (const float*)d_in[6];
    const float* gamma = (const float*)d_in[7];
    float* out = (float*)d_out;

    const int OUT_N = BB*CC*NN;        // 4,194,304
    const int ATT_N = BB*NN*NN;        // 67,108,864

    float* out_ptr = nullptr;
    float* att_ptr = nullptr;
    if (out_size >= OUT_N + ATT_N)      { out_ptr = out; att_ptr = out + OUT_N; }
    else if (out_size == ATT_N)         { att_ptr = out; }
    else                                { out_ptr = out; }

    cudaFuncSetAttribute(proj_qk_tc,
                         cudaFuncAttributeMaxDynamicSharedMemorySize, PSMEM);
    cudaFuncSetAttribute(attn_kernel,
                         cudaFuncAttributeMaxDynamicSharedMemorySize, ATTN_SMEM);

    proj_qk_tc<<<dim3(NN/64, BB), 256, PSMEM>>>(x, wq, bq, wk, bk);
    if (att_ptr && out_ptr) {
        attn_kernel<<<dim3(512, BB), 512, ATTN_SMEM>>>(att_ptr, x, gamma, out_ptr);
        out_fallback_kernel<<<BB*CC, 256>>>(x, gamma, wv, bv, att_ptr, out_ptr);
    } else if (att_ptr) {
        attn_kernel<<<dim3(512, BB), 512, ATTN_SMEM>>>(att_ptr, x, gamma, att_ptr);
    } else if (out_ptr) {
        copy_kernel<<<(OUT_N/4)/256, 256>>>(x, out_ptr);
        out_fallback_kernel<<<BB*CC, 256>>>(x, gamma, wv, bv, nullptr, out_ptr);
    }
}